// round 1
// baseline (speedup 1.0000x reference)
#include <cuda_runtime.h>
#include <math.h>
#include <float.h>

#define B_DIM 256
#define T_DIM 150
#define J_DIM 25
#define FEAT  9
#define WARPS 8
#define TPB   (WARPS * 32)

__device__ __forceinline__ float asqrt(float x) {
    float r;
    asm("sqrt.approx.f32 %0, %1;" : "=f"(r) : "f"(x));
    return r;
}

__global__ __launch_bounds__(TPB)
void knn_feat_kernel(const float* __restrict__ x, float* __restrict__ out) {
    // per-warp position tile (float4-padded for single LDS.128 per candidate)
    __shared__ float4 spos[WARPS][J_DIM];
    // per-warp partial feature sums for the block-level reduction
    __shared__ float  spart[WARPS][J_DIM * FEAT];

    const int b    = blockIdx.x;
    const int w    = threadIdx.x >> 5;
    const int lane = threadIdx.x & 31;

    float acc[FEAT];
#pragma unroll
    for (int f = 0; f < FEAT; ++f) acc[f] = 0.0f;

    const float* xb = x + (size_t)b * T_DIM * J_DIM * 3;

    for (int t = w; t < T_DIM; t += WARPS) {
        const float* xt = xb + t * (J_DIM * 3);

        __syncwarp();  // prior iteration's reads of spos complete before overwrite
        if (lane < J_DIM) {
            float px = xt[lane * 3 + 0];
            float py = xt[lane * 3 + 1];
            float pz = xt[lane * 3 + 2];
            spos[w][lane] = make_float4(px, py, pz, 0.0f);
        }
        __syncwarp();

        if (lane < J_DIM) {
            const float4 p = spos[w][lane];

            // 4 smallest squared distances (self excluded), sorted m0<=m1<=m2<=m3
            float m0 = FLT_MAX, m1 = FLT_MAX, m2 = FLT_MAX, m3 = FLT_MAX;
#pragma unroll
            for (int j = 0; j < J_DIM; ++j) {
                float4 q = spos[w][j];
                float dx = p.x - q.x;
                float dy = p.y - q.y;
                float dz = p.z - q.z;
                float s  = fmaf(dx, dx, fmaf(dy, dy, dz * dz));
                s = (j == lane) ? FLT_MAX : s;  // mask self
                // branch-free sorted insert (7 FMNMX)
                float hi;
                hi = fmaxf(s, m0); m0 = fminf(s, m0); s = hi;
                hi = fmaxf(s, m1); m1 = fminf(s, m1); s = hi;
                hi = fmaxf(s, m2); m2 = fminf(s, m2); s = hi;
                m3 = fminf(s, m3);
            }

            const float d1 = asqrt(m0);
            const float d2 = asqrt(m1);
            const float d3 = asqrt(m2);
            const float d4 = asqrt(m3);

            // k = 2
            const float a2 = 0.5f * (d1 + d2);
            const float s2 = fabsf(d2 - d1) * 0.70710678118654752f;  // |d1-d2|/sqrt(2)
            // k = 3
            const float a3 = (d1 + d2 + d3) * (1.0f / 3.0f);
            const float e1 = d1 - a3, e2 = d2 - a3, e3 = d3 - a3;
            const float s3 = asqrt(fmaf(e1, e1, fmaf(e2, e2, e3 * e3)) * 0.5f);
            // k = 4
            const float a4 = (d1 + d2 + d3 + d4) * 0.25f;
            const float g1 = d1 - a4, g2 = d2 - a4, g3 = d3 - a4, g4 = d4 - a4;
            const float s4 = asqrt(fmaf(g1, g1, fmaf(g2, g2, fmaf(g3, g3, g4 * g4)))
                                   * (1.0f / 3.0f));

            acc[0] += a2; acc[1] += s2; acc[2] += d1;
            acc[3] += a3; acc[4] += s3; acc[5] += d1;
            acc[6] += a4; acc[7] += s4; acc[8] += d1;
        }
    }

    // spill per-warp partials to SMEM
    if (lane < J_DIM) {
#pragma unroll
        for (int f = 0; f < FEAT; ++f)
            spart[w][lane * FEAT + f] = acc[f];
    }
    __syncthreads();

    // block-level reduce: 225 outputs for this b
    const int tid = threadIdx.x;
    if (tid < J_DIM * FEAT) {
        float s = 0.0f;
#pragma unroll
        for (int ww = 0; ww < WARPS; ++ww)
            s += spart[ww][tid];
        out[(size_t)b * (J_DIM * FEAT) + tid] = s * (1.0f / (float)T_DIM);
    }
}

extern "C" void kernel_launch(void* const* d_in, const int* in_sizes, int n_in,
                              void* d_out, int out_size) {
    const float* x = (const float*)d_in[0];
    float* out = (float*)d_out;
    knn_feat_kernel<<<B_DIM, TPB>>>(x, out);
}

// round 2
// speedup vs baseline: 1.0767x; 1.0767x over previous
#include <cuda_runtime.h>
#include <math.h>
#include <float.h>

#define B_DIM  256
#define T_DIM  150
#define J_DIM  25
#define FEAT   9
#define SPLIT  5
#define TCHUNK (T_DIM / SPLIT)          // 30 timesteps per block
#define TPB    250                      // 250 = 10 * 25 -> j = tid%25 is constant
#define ITEMS  (TCHUNK * J_DIM)         // 750 = 3 * 250

__device__ __forceinline__ float asqrt(float x) {
    float r;
    asm("sqrt.approx.f32 %0, %1;" : "=f"(r) : "f"(x));
    return r;
}

__global__ void zero_out_kernel(float* __restrict__ out, int n) {
    int i = blockIdx.x * blockDim.x + threadIdx.x;
    if (i < n) out[i] = 0.0f;
}

__global__ __launch_bounds__(TPB)
void knn_feat_kernel(const float* __restrict__ x, float* __restrict__ out) {
    __shared__ float4 spos[TCHUNK][J_DIM];     // 12 KB
    __shared__ float  spart[J_DIM * FEAT];     // 900 B

    const int b   = blockIdx.x;
    const int s   = blockIdx.y;
    const int tid = threadIdx.x;
    const int t0  = s * TCHUNK;

    // cooperative load of the 30x25 position tile (2250 consecutive floats)
    const float* xb = x + ((size_t)b * T_DIM + t0) * (J_DIM * 3);
    for (int i = tid; i < ITEMS; i += TPB) {
        float px = xb[3 * i + 0];
        float py = xb[3 * i + 1];
        float pz = xb[3 * i + 2];
        spos[i / J_DIM][i % J_DIM] = make_float4(px, py, pz, 0.0f);
    }
    if (tid < J_DIM * FEAT) spart[tid] = 0.0f;
    __syncthreads();

    const int jidx   = tid % J_DIM;   // constant per thread
    const int ltbase = tid / J_DIM;   // 0..9

    float acc[FEAT];
#pragma unroll
    for (int f = 0; f < FEAT; ++f) acc[f] = 0.0f;

#pragma unroll
    for (int it = 0; it < 3; ++it) {
        const int lt = ltbase + it * 10;
        const float4 p = spos[lt][jidx];

        float m0 = FLT_MAX, m1 = FLT_MAX, m2 = FLT_MAX, m3 = FLT_MAX;
#pragma unroll
        for (int j = 0; j < J_DIM; ++j) {
            float4 q = spos[lt][j];
            float dx = p.x - q.x;
            float dy = p.y - q.y;
            float dz = p.z - q.z;
            float sq = fmaf(dx, dx, fmaf(dy, dy, dz * dz));
            sq = (j == jidx) ? FLT_MAX : sq;  // mask self
            float hi;
            hi = fmaxf(sq, m0); m0 = fminf(sq, m0); sq = hi;
            hi = fmaxf(sq, m1); m1 = fminf(sq, m1); sq = hi;
            hi = fmaxf(sq, m2); m2 = fminf(sq, m2); sq = hi;
            m3 = fminf(sq, m3);
        }

        const float d1 = asqrt(m0);
        const float d2 = asqrt(m1);
        const float d3 = asqrt(m2);
        const float d4 = asqrt(m3);

        // k = 2
        const float a2 = 0.5f * (d1 + d2);
        const float s2 = fabsf(d2 - d1) * 0.70710678118654752f;
        // k = 3
        const float a3 = (d1 + d2 + d3) * (1.0f / 3.0f);
        const float e1 = d1 - a3, e2 = d2 - a3, e3 = d3 - a3;
        const float s3 = asqrt(fmaf(e1, e1, fmaf(e2, e2, e3 * e3)) * 0.5f);
        // k = 4
        const float a4 = (d1 + d2 + d3 + d4) * 0.25f;
        const float g1 = d1 - a4, g2 = d2 - a4, g3 = d3 - a4, g4 = d4 - a4;
        const float s4 = asqrt(fmaf(g1, g1, fmaf(g2, g2, fmaf(g3, g3, g4 * g4)))
                               * (1.0f / 3.0f));

        acc[0] += a2; acc[1] += s2; acc[2] += d1;
        acc[3] += a3; acc[4] += s3; acc[5] += d1;
        acc[6] += a4; acc[7] += s4; acc[8] += d1;
    }

    // combine the 10 threads sharing each j via SMEM atomics (one round)
#pragma unroll
    for (int f = 0; f < FEAT; ++f)
        atomicAdd(&spart[jidx * FEAT + f], acc[f]);
    __syncthreads();

    // one global atomic per output element per block (5 blocks contend per addr)
    if (tid < J_DIM * FEAT)
        atomicAdd(&out[(size_t)b * (J_DIM * FEAT) + tid],
                  spart[tid] * (1.0f / (float)T_DIM));
}

extern "C" void kernel_launch(void* const* d_in, const int* in_sizes, int n_in,
                              void* d_out, int out_size) {
    const float* x = (const float*)d_in[0];
    float* out = (float*)d_out;

    zero_out_kernel<<<(out_size + 255) / 256, 256>>>(out, out_size);
    dim3 grid(B_DIM, SPLIT);
    knn_feat_kernel<<<grid, TPB>>>(x, out);
}